// round 1
// baseline (speedup 1.0000x reference)
#include <cuda_runtime.h>
#include <cuda_bf16.h>
#include <math.h>

#define Bb 32
#define Ss 512
#define Hh 1024
#define Mm 8
#define NTOK (Bb * Ss)       // 16384
#define NSPAN (NTOK * Mm)    // 131072
#define TOPK 4915            // int(0.3 * B * S)

// ---------------- device scratch (no allocations allowed) ----------------
__device__ float g_query[Hh];
__device__ float g_e[NTOK];
__device__ float g_f[NTOK];
__device__ unsigned int g_keys[NSPAN];
__device__ float g_sp_sum;   // sum of softplus(-score) over gold spans
__device__ int   g_gold_cnt;
__device__ int   g_valid_cnt;

__device__ __forceinline__ float warpReduceF(float v) {
    #pragma unroll
    for (int o = 16; o; o >>= 1) v += __shfl_xor_sync(0xffffffffu, v, o);
    return v;
}
__device__ __forceinline__ int warpReduceI(int v) {
    #pragma unroll
    for (int o = 16; o; o >>= 1) v += __shfl_xor_sync(0xffffffffu, v, o);
    return v;
}

// ---------------- kernel 1: query = w_in @ term_weight + b_in ----------------
__global__ void k_query(const float* __restrict__ w_in,
                        const float* __restrict__ tw,
                        const float* __restrict__ b_in) {
    int r = blockIdx.x;  // row 0..1023
    if (r == 0 && threadIdx.x == 0) {
        g_sp_sum = 0.0f; g_gold_cnt = 0; g_valid_cnt = 0;
    }
    const float4* wr = reinterpret_cast<const float4*>(w_in + (size_t)r * Hh);
    const float4* t4 = reinterpret_cast<const float4*>(tw);
    int i = threadIdx.x;                       // 256 threads * float4 = 1024
    float4 a = wr[i];
    float4 b = t4[i];
    float acc = a.x * b.x + a.y * b.y + a.z * b.z + a.w * b.w;

    __shared__ float sh[8];
    float v = warpReduceF(acc);
    if ((threadIdx.x & 31) == 0) sh[threadIdx.x >> 5] = v;
    __syncthreads();
    if (threadIdx.x < 8) {
        float x = sh[threadIdx.x];
        #pragma unroll
        for (int o = 4; o; o >>= 1) x += __shfl_xor_sync(0xffu, x, o);
        if (threadIdx.x == 0) g_query[r] = x + b_in[r];
    }
}

// ---------------- kernel 2: e[t]=hidden[t]·query, f[t]=hidden[t]·score_w ----------------
// 8 warps per block, one token per warp. q/w staged in shared once per block.
__global__ void k_ef(const float* __restrict__ hidden,
                     const float* __restrict__ score_w) {
    __shared__ float shq[Hh];
    __shared__ float shw[Hh];
    for (int i = threadIdx.x; i < Hh; i += blockDim.x) {
        shq[i] = g_query[i];
        shw[i] = score_w[i];
    }
    __syncthreads();

    int warp = threadIdx.x >> 5, lane = threadIdx.x & 31;
    int t = blockIdx.x * 8 + warp;
    const float4* hp = reinterpret_cast<const float4*>(hidden + (size_t)t * Hh);
    float e = 0.0f, f = 0.0f;
    #pragma unroll
    for (int c = 0; c < 8; c++) {
        int j = c * 32 + lane;                 // float4 index within row
        float4 h = hp[j];
        int k = j * 4;
        e += h.x * shq[k] + h.y * shq[k + 1] + h.z * shq[k + 2] + h.w * shq[k + 3];
        f += h.x * shw[k] + h.y * shw[k + 1] + h.z * shw[k + 2] + h.w * shw[k + 3];
    }
    e = warpReduceF(e);
    f = warpReduceF(f);
    if (lane == 0) { g_e[t] = e; g_f[t] = f; }
}

// ---------------- kernel 3: online softmax scores + keys + loss accumulators ----------------
__global__ void k_scores(const float* __restrict__ score_b_p,
                         const int* __restrict__ seq_len,
                         const int* __restrict__ gold_mask) {
    int t = blockIdx.x * blockDim.x + threadIdx.x;  // token index (b*S+s)
    float sp_local = 0.0f;
    int gold_local = 0, valid_local = 0;

    if (t < NTOK) {
        int b = t >> 9, s = t & (Ss - 1);
        int L = seq_len[b];
        float sb = score_b_p[0];
        float m = -INFINITY, den = 0.0f, num = 0.0f;
        #pragma unroll
        for (int l = 0; l < Mm; l++) {
            int pos = s + l; if (pos > Ss - 1) pos = Ss - 1;   // clip (result unused if invalid)
            float el = g_e[(b << 9) + pos];
            float fl = g_f[(b << 9) + pos];
            float mn = fmaxf(m, el);
            float sc = expf(m - mn);      // 0 on first iter (m=-inf)
            float we = expf(el - mn);
            den = den * sc + we;
            num = num * sc + we * fl;
            m = mn;
            float score = num / den + sb;

            unsigned key;
            if (s + l + 1 <= L) {
                unsigned u = __float_as_uint(score);
                key = u ^ ((u >> 31) ? 0xFFFFFFFFu : 0x80000000u);
                valid_local++;
                if (gold_mask[t * Mm + l] == 0) {
                    gold_local++;
                    // softplus(-score) = max(-score,0) + log1p(exp(-|score|))
                    sp_local += fmaxf(-score, 0.0f) + log1pf(expf(-fabsf(score)));
                }
            } else {
                key = 0x007FFFFFu;  // flipped key of -inf
            }
            g_keys[t * Mm + l] = key;
        }
    }

    // block reduce then one atomic per block
    __shared__ float shf[8];
    __shared__ int shg[8], shv[8];
    float sp = warpReduceF(sp_local);
    int gd = warpReduceI(gold_local);
    int vd = warpReduceI(valid_local);
    if ((threadIdx.x & 31) == 0) {
        int w = threadIdx.x >> 5;
        shf[w] = sp; shg[w] = gd; shv[w] = vd;
    }
    __syncthreads();
    if (threadIdx.x == 0) {
        float S1 = 0.0f; int S2 = 0, S3 = 0;
        #pragma unroll
        for (int w = 0; w < 8; w++) { S1 += shf[w]; S2 += shg[w]; S3 += shv[w]; }
        atomicAdd(&g_sp_sum, S1);
        atomicAdd(&g_gold_cnt, S2);
        atomicAdd(&g_valid_cnt, S3);
    }
}

// ---------------- kernel 4: exact top-K radix select + outputs ----------------
__global__ void k_select(const int* __restrict__ seq_len,
                         const int* __restrict__ gold_mask,
                         float* __restrict__ out) {
    __shared__ int hist[256];
    __shared__ unsigned int s_pref, s_mask;
    __shared__ int s_rem;
    __shared__ int s_ggt, s_tiecnt;
    __shared__ int tie_idx[4096];

    int tid = threadIdx.x;
    if (tid == 0) { s_pref = 0u; s_mask = 0u; s_rem = TOPK; }
    __syncthreads();

    // 4 passes, 8 bits each, MSB first. No variable 32-bit shifts (mask form).
    for (int p = 0; p < 4; p++) {
        int shift = 24 - 8 * p;
        if (tid < 256) hist[tid] = 0;
        __syncthreads();
        unsigned pref = s_pref, mask = s_mask;
        for (int i = tid; i < NSPAN; i += blockDim.x) {
            unsigned key = g_keys[i];
            if ((key & mask) == pref)
                atomicAdd(&hist[(key >> shift) & 255], 1);
        }
        __syncthreads();
        if (tid == 0) {
            int cum = 0, rem = s_rem;
            for (int bbin = 255; bbin >= 0; bbin--) {
                int c = hist[bbin];
                if (cum + c >= rem) {
                    s_pref = pref | ((unsigned)bbin << shift);
                    s_mask = mask | (0xFFu << shift);
                    s_rem = rem - cum;   // rank within the equal group (>=1)
                    break;
                }
                cum += c;
            }
        }
        __syncthreads();
    }

    unsigned T = s_pref;   // exact key of K-th largest
    int rem = s_rem;       // # of tie elements included in top-K
    if (tid == 0) { s_ggt = 0; s_tiecnt = 0; }
    __syncthreads();

    int gg = 0;
    for (int i = tid; i < NSPAN; i += blockDim.x) {
        unsigned key = g_keys[i];
        if (key > T) {
            int l = i & 7, t = i >> 3, b = t >> 9, s = t & (Ss - 1);
            if (s + l + 1 <= seq_len[b] && gold_mask[i] == 0) gg++;
        } else if (key == T) {
            int pos = atomicAdd(&s_tiecnt, 1);
            if (pos < 4096) tie_idx[pos] = i;
        }
    }
    atomicAdd(&s_ggt, gg);
    __syncthreads();

    if (tid == 0) {
        int need = rem;
        int cnt = s_tiecnt; if (cnt > 4096) cnt = 4096;
        int gtie = 0;
        if (need >= cnt) {
            // take all ties
            for (int j = 0; j < cnt; j++) {
                int i = tie_idx[j];
                int l = i & 7, t = i >> 3, b = t >> 9, s = t & (Ss - 1);
                if (s + l + 1 <= seq_len[b] && gold_mask[i] == 0) gtie++;
            }
        } else {
            // take `need` smallest indices (matches top_k index-order tie break)
            for (int j = 0; j < need; j++) {
                int best = 0x7FFFFFFF, bi = -1;
                for (int q = 0; q < cnt; q++) {
                    int v = tie_idx[q];
                    if (v >= 0 && v < best) { best = v; bi = q; }
                }
                tie_idx[bi] = -1;
                int i = best;
                int l = i & 7, t = i >> 3, b = t >> 9, s = t & (Ss - 1);
                if (s + l + 1 <= seq_len[b] && gold_mask[i] == 0) gtie++;
            }
        }
        int right = s_ggt + gtie;
        float nv = (float)g_valid_cnt;
        float loss = (g_sp_sum + 0.6931471805599453f * (float)(g_valid_cnt - g_gold_cnt)) / nv;
        out[0] = loss;
        out[1] = (float)right / (float)TOPK;
    }
}

// ---------------- launch ----------------
extern "C" void kernel_launch(void* const* d_in, const int* in_sizes, int n_in,
                              void* d_out, int out_size) {
    const float* hidden  = (const float*)d_in[0];   // [B,S,H]
    const float* tw      = (const float*)d_in[1];   // [H]
    const float* w_in    = (const float*)d_in[2];   // [H,H]
    const float* b_in    = (const float*)d_in[3];   // [H]
    const float* score_w = (const float*)d_in[4];   // [H]
    const float* score_b = (const float*)d_in[5];   // [1]
    const int*   seq_len = (const int*)d_in[6];     // [B]
    const int*   gold    = (const int*)d_in[7];     // [B,S,M]
    float* out = (float*)d_out;

    k_query <<<Hh, 256>>>(w_in, tw, b_in);
    k_ef    <<<NTOK / 8, 256>>>(hidden, score_w);
    k_scores<<<NTOK / 256, 256>>>(score_b, seq_len, gold);
    k_select<<<1, 1024>>>(seq_len, gold, out);
}

// round 2
// speedup vs baseline: 2.0172x; 2.0172x over previous
#include <cuda_runtime.h>
#include <cuda_bf16.h>
#include <math.h>

#define Bb 32
#define Ss 512
#define Hh 1024
#define Mm 8
#define NTOK (Bb * Ss)       // 16384
#define NSPAN (NTOK * Mm)    // 131072
#define TOPK 4915            // int(0.3 * B * S)
#define NBIN 65536
#define TIE_CAP 16384

// ---------------- device scratch ----------------
__device__ float g_query[Hh];
__device__ float g_e[NTOK];
__device__ float g_f[NTOK];
__device__ unsigned int g_keys[NSPAN];
__device__ int   g_hist16[NBIN];
__device__ float g_sp_sum;
__device__ int   g_gold_cnt;
__device__ int   g_valid_cnt;
__device__ unsigned int g_selP;   // 16-bit prefix of K-th largest
__device__ int   g_selRem;        // residual rank within prefix bucket (>=1)
__device__ int   g_right;         // gold count among strictly-above keys
__device__ int   g_tiecnt;
__device__ int   g_tie[TIE_CAP];

__device__ __forceinline__ float warpReduceF(float v) {
    #pragma unroll
    for (int o = 16; o; o >>= 1) v += __shfl_xor_sync(0xffffffffu, v, o);
    return v;
}
__device__ __forceinline__ int warpReduceI(int v) {
    #pragma unroll
    for (int o = 16; o; o >>= 1) v += __shfl_xor_sync(0xffffffffu, v, o);
    return v;
}

// ---------------- kernel 1: query = w_in @ term_weight + b_in; init state ----------------
__global__ void k_query(const float* __restrict__ w_in,
                        const float* __restrict__ tw,
                        const float* __restrict__ b_in) {
    int r = blockIdx.x;
    if (r == 0 && threadIdx.x == 0) {
        g_sp_sum = 0.0f; g_gold_cnt = 0; g_valid_cnt = 0;
        g_right = 0; g_tiecnt = 0;
    }
    const float4* wr = reinterpret_cast<const float4*>(w_in + (size_t)r * Hh);
    const float4* t4 = reinterpret_cast<const float4*>(tw);
    int i = threadIdx.x;
    float4 a = wr[i];
    float4 b = t4[i];
    float acc = a.x * b.x + a.y * b.y + a.z * b.z + a.w * b.w;

    __shared__ float sh[8];
    float v = warpReduceF(acc);
    if ((threadIdx.x & 31) == 0) sh[threadIdx.x >> 5] = v;
    __syncthreads();
    if (threadIdx.x < 8) {
        float x = sh[threadIdx.x];
        #pragma unroll
        for (int o = 4; o; o >>= 1) x += __shfl_xor_sync(0xffu, x, o);
        if (threadIdx.x == 0) g_query[r] = x + b_in[r];
    }
}

// ---------------- kernel 2: e/f dot products; also zeroes hist ----------------
__global__ void k_ef(const float* __restrict__ hidden,
                     const float* __restrict__ score_w) {
    __shared__ float shq[Hh];
    __shared__ float shw[Hh];
    int gid = blockIdx.x * blockDim.x + threadIdx.x;
    if (gid < NBIN) g_hist16[gid] = 0;
    for (int i = threadIdx.x; i < Hh; i += blockDim.x) {
        shq[i] = g_query[i];
        shw[i] = score_w[i];
    }
    __syncthreads();

    int warp = threadIdx.x >> 5, lane = threadIdx.x & 31;
    int t = blockIdx.x * 8 + warp;
    const float4* hp = reinterpret_cast<const float4*>(hidden + (size_t)t * Hh);
    float e = 0.0f, f = 0.0f;
    #pragma unroll
    for (int c = 0; c < 8; c++) {
        int j = c * 32 + lane;
        float4 h = hp[j];
        int k = j * 4;
        e += h.x * shq[k] + h.y * shq[k + 1] + h.z * shq[k + 2] + h.w * shq[k + 3];
        f += h.x * shw[k] + h.y * shw[k + 1] + h.z * shw[k + 2] + h.w * shw[k + 3];
    }
    e = warpReduceF(e);
    f = warpReduceF(f);
    if (lane == 0) { g_e[t] = e; g_f[t] = f; }
}

// ---------------- kernel 3: scores, keys, loss accum, 16-bit histogram ----------------
__global__ void k_scores(const float* __restrict__ score_b_p,
                         const int* __restrict__ seq_len,
                         const int* __restrict__ gold_mask) {
    int t = blockIdx.x * blockDim.x + threadIdx.x;
    float sp_local = 0.0f;
    int gold_local = 0, valid_local = 0;

    if (t < NTOK) {
        int b = t >> 9, s = t & (Ss - 1);
        int L = seq_len[b];
        float sb = score_b_p[0];
        float m = -INFINITY, den = 0.0f, num = 0.0f;
        #pragma unroll
        for (int l = 0; l < Mm; l++) {
            int pos = s + l; if (pos > Ss - 1) pos = Ss - 1;
            float el = g_e[(b << 9) + pos];
            float fl = g_f[(b << 9) + pos];
            float mn = fmaxf(m, el);
            float sc = expf(m - mn);
            float we = expf(el - mn);
            den = den * sc + we;
            num = num * sc + we * fl;
            m = mn;
            float score = num / den + sb;

            unsigned key;
            if (s + l + 1 <= L) {
                unsigned u = __float_as_uint(score);
                key = u ^ ((u >> 31) ? 0xFFFFFFFFu : 0x80000000u);
                valid_local++;
                if (gold_mask[t * Mm + l] == 0) {
                    gold_local++;
                    sp_local += fmaxf(-score, 0.0f) + log1pf(expf(-fabsf(score)));
                }
            } else {
                key = 0x007FFFFFu;  // flipped -inf
            }
            g_keys[t * Mm + l] = key;
            atomicAdd(&g_hist16[key >> 16], 1);
        }
    }

    __shared__ float shf[8];
    __shared__ int shg[8], shv[8];
    float sp = warpReduceF(sp_local);
    int gd = warpReduceI(gold_local);
    int vd = warpReduceI(valid_local);
    if ((threadIdx.x & 31) == 0) {
        int w = threadIdx.x >> 5;
        shf[w] = sp; shg[w] = gd; shv[w] = vd;
    }
    __syncthreads();
    if (threadIdx.x == 0) {
        float S1 = 0.0f; int S2 = 0, S3 = 0;
        #pragma unroll
        for (int w = 0; w < 8; w++) { S1 += shf[w]; S2 += shg[w]; S3 += shv[w]; }
        atomicAdd(&g_sp_sum, S1);
        atomicAdd(&g_gold_cnt, S2);
        atomicAdd(&g_valid_cnt, S3);
    }
}

// ---------------- kernel 4: scan 65536-bin hist, find prefix + rem ----------------
__global__ void k_scan() {
    __shared__ int sh[1024];
    int tid = threadIdx.x;
    // chunk = 64 bins; chunk i covers bins [i*64, i*64+64)
    int base = tid * 64;
    int csum = 0;
    #pragma unroll 8
    for (int j = 0; j < 64; j++) csum += g_hist16[base + j];
    sh[tid] = csum;
    __syncthreads();
    // inclusive suffix scan (sh[i] = sum over chunks >= i)
    for (int off = 1; off < 1024; off <<= 1) {
        int v = (tid + off < 1024) ? sh[tid + off] : 0;
        __syncthreads();
        sh[tid] += v;
        __syncthreads();
    }
    int incl = sh[tid];
    int above = incl - csum;  // count in chunks strictly above this chunk
    if (above < TOPK && incl >= TOPK) {
        // boundary chunk: walk bins from high to low
        int cum = above;
        for (int b = 63; b >= 0; b--) {
            int c = g_hist16[base + b];
            if (cum + c >= TOPK) {
                g_selP = (unsigned)(base + b);
                g_selRem = TOPK - cum;
                break;
            }
            cum += c;
        }
    }
}

// ---------------- kernel 5: parallel count above threshold + tie collection ----------------
__global__ void k_count(const int* __restrict__ seq_len,
                        const int* __restrict__ gold_mask) {
    unsigned P = g_selP;
    int tid = blockIdx.x * blockDim.x + threadIdx.x;
    int nthreads = gridDim.x * blockDim.x;
    int gg = 0;
    for (int i = tid; i < NSPAN; i += nthreads) {
        unsigned top = g_keys[i] >> 16;
        if (top > P) {
            int l = i & 7, t = i >> 3, b = t >> 9, s = t & (Ss - 1);
            if (s + l + 1 <= seq_len[b] && gold_mask[i] == 0) gg++;
        } else if (top == P) {
            int pos = atomicAdd(&g_tiecnt, 1);
            if (pos < TIE_CAP) g_tie[pos] = i;
        }
    }
    gg = warpReduceI(gg);
    __shared__ int shc[8];
    if ((threadIdx.x & 31) == 0) shc[threadIdx.x >> 5] = gg;
    __syncthreads();
    if (threadIdx.x == 0) {
        int S = 0;
        for (int w = 0; w < (int)(blockDim.x >> 5); w++) S += shc[w];
        if (S) atomicAdd(&g_right, S);
    }
}

// ---------------- kernel 6: exact rank within tie bucket + outputs ----------------
__global__ void k_final(const int* __restrict__ seq_len,
                        const int* __restrict__ gold_mask,
                        float* __restrict__ out) {
    int tid = threadIdx.x;
    int n = g_tiecnt; if (n > TIE_CAP) n = TIE_CAP;
    int rem = g_selRem;
    __shared__ int s_g;
    if (tid == 0) s_g = 0;
    __syncthreads();

    int gtie = 0;
    for (int j = tid; j < n; j += blockDim.x) {
        int ij = g_tie[j];
        unsigned kj = g_keys[ij];
        // rank among bucket by (key desc, index asc)
        int rank = 0;
        for (int q = 0; q < n; q++) {
            int iq = g_tie[q];
            unsigned kq = g_keys[iq];
            if (kq > kj || (kq == kj && iq < ij)) rank++;
        }
        if (rank < rem) {
            int l = ij & 7, t = ij >> 3, b = t >> 9, s = t & (Ss - 1);
            if (s + l + 1 <= seq_len[b] && gold_mask[ij] == 0) gtie++;
        }
    }
    gtie = warpReduceI(gtie);
    if ((threadIdx.x & 31) == 0 && gtie) atomicAdd(&s_g, gtie);
    __syncthreads();

    if (tid == 0) {
        int right = g_right + s_g;
        float nv = (float)g_valid_cnt;
        float loss = (g_sp_sum + 0.6931471805599453f * (float)(g_valid_cnt - g_gold_cnt)) / nv;
        out[0] = loss;
        out[1] = (float)right / (float)TOPK;
    }
}

// ---------------- launch ----------------
extern "C" void kernel_launch(void* const* d_in, const int* in_sizes, int n_in,
                              void* d_out, int out_size) {
    const float* hidden  = (const float*)d_in[0];
    const float* tw      = (const float*)d_in[1];
    const float* w_in    = (const float*)d_in[2];
    const float* b_in    = (const float*)d_in[3];
    const float* score_w = (const float*)d_in[4];
    const float* score_b = (const float*)d_in[5];
    const int*   seq_len = (const int*)d_in[6];
    const int*   gold    = (const int*)d_in[7];
    float* out = (float*)d_out;

    k_query <<<Hh, 256>>>(w_in, tw, b_in);
    k_ef    <<<NTOK / 8, 256>>>(hidden, score_w);
    k_scores<<<NTOK / 256, 256>>>(score_b, seq_len, gold);
    k_scan  <<<1, 1024>>>();
    k_count <<<148, 256>>>(seq_len, gold);
    k_final <<<1, 1024>>>(seq_len, gold, out);
}

// round 3
// speedup vs baseline: 3.2344x; 1.6034x over previous
#include <cuda_runtime.h>
#include <cuda_bf16.h>
#include <math.h>

#define Bb 32
#define Ss 512
#define Hh 1024
#define Mm 8
#define NTOK (Bb * Ss)       // 16384
#define NSPAN (NTOK * Mm)    // 131072
#define TOPK 4915            // int(0.3 * B * S)
#define NBIN 65536
#define NCHUNK 1024          // 64 bins per chunk
#define TIE_CAP 16384

// ---------------- device scratch ----------------
__device__ float g_query[Hh];
__device__ float g_e[NTOK];
__device__ float g_f[NTOK];
__device__ unsigned int g_keys[NSPAN];
__device__ int   g_hist16[NBIN];
__device__ int   g_chunk[NCHUNK];
__device__ float g_sp_sum;
__device__ int   g_gold_cnt;
__device__ int   g_valid_cnt;
__device__ unsigned int g_selP;   // 16-bit prefix of K-th largest
__device__ int   g_selRem;        // residual rank within prefix bucket (>=1)
__device__ int   g_right;         // gold count among strictly-above keys
__device__ int   g_tiecnt;
__device__ int   g_tie[TIE_CAP];

__device__ __forceinline__ float warpReduceF(float v) {
    #pragma unroll
    for (int o = 16; o; o >>= 1) v += __shfl_xor_sync(0xffffffffu, v, o);
    return v;
}
__device__ __forceinline__ int warpReduceI(int v) {
    #pragma unroll
    for (int o = 16; o; o >>= 1) v += __shfl_xor_sync(0xffffffffu, v, o);
    return v;
}

// ---------------- kernel 1: query = w_in @ term_weight + b_in; init state ----------------
__global__ void k_query(const float* __restrict__ w_in,
                        const float* __restrict__ tw,
                        const float* __restrict__ b_in) {
    int r = blockIdx.x;
    if (r == 0 && threadIdx.x == 0) {
        g_sp_sum = 0.0f; g_gold_cnt = 0; g_valid_cnt = 0;
        g_right = 0; g_tiecnt = 0;
    }
    const float4* wr = reinterpret_cast<const float4*>(w_in + (size_t)r * Hh);
    const float4* t4 = reinterpret_cast<const float4*>(tw);
    int i = threadIdx.x;
    float4 a = wr[i];
    float4 b = t4[i];
    float acc = a.x * b.x + a.y * b.y + a.z * b.z + a.w * b.w;

    __shared__ float sh[8];
    float v = warpReduceF(acc);
    if ((threadIdx.x & 31) == 0) sh[threadIdx.x >> 5] = v;
    __syncthreads();
    if (threadIdx.x < 8) {
        float x = sh[threadIdx.x];
        #pragma unroll
        for (int o = 4; o; o >>= 1) x += __shfl_xor_sync(0xffu, x, o);
        if (threadIdx.x == 0) g_query[r] = x + b_in[r];
    }
}

// ---------------- kernel 2: e/f dot products; also zeroes hist ----------------
__global__ void k_ef(const float* __restrict__ hidden,
                     const float* __restrict__ score_w) {
    __shared__ float shq[Hh];
    __shared__ float shw[Hh];
    int gid = blockIdx.x * blockDim.x + threadIdx.x;
    if (gid < NBIN) g_hist16[gid] = 0;
    for (int i = threadIdx.x; i < Hh; i += blockDim.x) {
        shq[i] = g_query[i];
        shw[i] = score_w[i];
    }
    __syncthreads();

    int warp = threadIdx.x >> 5, lane = threadIdx.x & 31;
    int t = blockIdx.x * 8 + warp;
    const float4* hp = reinterpret_cast<const float4*>(hidden + (size_t)t * Hh);
    float e = 0.0f, f = 0.0f;
    #pragma unroll
    for (int c = 0; c < 8; c++) {
        int j = c * 32 + lane;
        float4 h = hp[j];
        int k = j * 4;
        e += h.x * shq[k] + h.y * shq[k + 1] + h.z * shq[k + 2] + h.w * shq[k + 3];
        f += h.x * shw[k] + h.y * shw[k + 1] + h.z * shw[k + 2] + h.w * shw[k + 3];
    }
    e = warpReduceF(e);
    f = warpReduceF(f);
    if (lane == 0) { g_e[t] = e; g_f[t] = f; }
}

// ---------------- kernel 3: scores, keys, loss accum, 16-bit histogram ----------------
__global__ void k_scores(const float* __restrict__ score_b_p,
                         const int* __restrict__ seq_len,
                         const int* __restrict__ gold_mask) {
    int t = blockIdx.x * blockDim.x + threadIdx.x;
    float sp_local = 0.0f;
    int gold_local = 0, valid_local = 0;

    if (t < NTOK) {
        int b = t >> 9, s = t & (Ss - 1);
        int L = seq_len[b];
        float sb = score_b_p[0];
        float m = -INFINITY, den = 0.0f, num = 0.0f;
        #pragma unroll
        for (int l = 0; l < Mm; l++) {
            int pos = s + l; if (pos > Ss - 1) pos = Ss - 1;
            float el = g_e[(b << 9) + pos];
            float fl = g_f[(b << 9) + pos];
            float mn = fmaxf(m, el);
            float sc = expf(m - mn);
            float we = expf(el - mn);
            den = den * sc + we;
            num = num * sc + we * fl;
            m = mn;
            float score = num / den + sb;

            unsigned key;
            if (s + l + 1 <= L) {
                unsigned u = __float_as_uint(score);
                key = u ^ ((u >> 31) ? 0xFFFFFFFFu : 0x80000000u);
                valid_local++;
                if (gold_mask[t * Mm + l] == 0) {
                    gold_local++;
                    sp_local += fmaxf(-score, 0.0f) + log1pf(expf(-fabsf(score)));
                }
            } else {
                key = 0x007FFFFFu;  // flipped -inf
            }
            g_keys[t * Mm + l] = key;
            atomicAdd(&g_hist16[key >> 16], 1);
        }
    }

    __shared__ float shf[8];
    __shared__ int shg[8], shv[8];
    float sp = warpReduceF(sp_local);
    int gd = warpReduceI(gold_local);
    int vd = warpReduceI(valid_local);
    if ((threadIdx.x & 31) == 0) {
        int w = threadIdx.x >> 5;
        shf[w] = sp; shg[w] = gd; shv[w] = vd;
    }
    __syncthreads();
    if (threadIdx.x == 0) {
        float S1 = 0.0f; int S2 = 0, S3 = 0;
        #pragma unroll
        for (int w = 0; w < 8; w++) { S1 += shf[w]; S2 += shg[w]; S3 += shv[w]; }
        atomicAdd(&g_sp_sum, S1);
        atomicAdd(&g_gold_cnt, S2);
        atomicAdd(&g_valid_cnt, S3);
    }
}

// ---------------- kernel 4a: coalesced reduce 65536 bins -> 1024 chunk sums ----------------
// 64 blocks x 1024 threads; block b covers bins [b*1024, (b+1)*1024) = chunks [b*16, b*16+16)
__global__ void k_reduce() {
    __shared__ int wsum[32];
    int tid = threadIdx.x;
    int v = g_hist16[blockIdx.x * 1024 + tid];   // fully coalesced
    v = warpReduceI(v);
    if ((tid & 31) == 0) wsum[tid >> 5] = v;
    __syncthreads();
    // chunk c (64 bins) = warps 2c, 2c+1
    if (tid < 16) {
        g_chunk[blockIdx.x * 16 + tid] = wsum[2 * tid] + wsum[2 * tid + 1];
    }
}

// ---------------- kernel 4b: suffix scan 1024 chunks, locate prefix + rem ----------------
__global__ void k_scan2() {
    __shared__ int sh[NCHUNK];
    int tid = threadIdx.x;
    int csum = g_chunk[tid];                     // coalesced 4KB
    sh[tid] = csum;
    __syncthreads();
    for (int off = 1; off < NCHUNK; off <<= 1) {
        int v = (tid + off < NCHUNK) ? sh[tid + off] : 0;
        __syncthreads();
        sh[tid] += v;
        __syncthreads();
    }
    int incl = sh[tid];
    int above = incl - csum;
    if (above < TOPK && incl >= TOPK) {
        int base = tid * 64;
        int cum = above;
        for (int b = 63; b >= 0; b--) {
            int c = g_hist16[base + b];
            if (cum + c >= TOPK) {
                g_selP = (unsigned)(base + b);
                g_selRem = TOPK - cum;
                break;
            }
            cum += c;
        }
    }
}

// ---------------- kernel 5: parallel count above threshold + tie collection ----------------
__global__ void k_count(const int* __restrict__ seq_len,
                        const int* __restrict__ gold_mask) {
    unsigned P = g_selP;
    int tid = blockIdx.x * blockDim.x + threadIdx.x;
    int nthreads = gridDim.x * blockDim.x;
    int gg = 0;
    for (int i = tid; i < NSPAN; i += nthreads) {
        unsigned top = g_keys[i] >> 16;
        if (top > P) {
            int l = i & 7, t = i >> 3, b = t >> 9, s = t & (Ss - 1);
            if (s + l + 1 <= seq_len[b] && gold_mask[i] == 0) gg++;
        } else if (top == P) {
            int pos = atomicAdd(&g_tiecnt, 1);
            if (pos < TIE_CAP) g_tie[pos] = i;
        }
    }
    gg = warpReduceI(gg);
    __shared__ int shc[8];
    if ((threadIdx.x & 31) == 0) shc[threadIdx.x >> 5] = gg;
    __syncthreads();
    if (threadIdx.x == 0) {
        int S = 0;
        for (int w = 0; w < (int)(blockDim.x >> 5); w++) S += shc[w];
        if (S) atomicAdd(&g_right, S);
    }
}

// ---------------- kernel 6: exact rank within tie bucket + outputs ----------------
__global__ void k_final(const int* __restrict__ seq_len,
                        const int* __restrict__ gold_mask,
                        float* __restrict__ out) {
    int tid = threadIdx.x;
    int n = g_tiecnt; if (n > TIE_CAP) n = TIE_CAP;
    int rem = g_selRem;
    __shared__ int s_g;
    if (tid == 0) s_g = 0;
    __syncthreads();

    int gtie = 0;
    for (int j = tid; j < n; j += blockDim.x) {
        int ij = g_tie[j];
        unsigned kj = g_keys[ij];
        int rank = 0;
        for (int q = 0; q < n; q++) {
            int iq = g_tie[q];
            unsigned kq = g_keys[iq];
            if (kq > kj || (kq == kj && iq < ij)) rank++;
        }
        if (rank < rem) {
            int l = ij & 7, t = ij >> 3, b = t >> 9, s = t & (Ss - 1);
            if (s + l + 1 <= seq_len[b] && gold_mask[ij] == 0) gtie++;
        }
    }
    gtie = warpReduceI(gtie);
    if ((threadIdx.x & 31) == 0 && gtie) atomicAdd(&s_g, gtie);
    __syncthreads();

    if (tid == 0) {
        int right = g_right + s_g;
        float nv = (float)g_valid_cnt;
        float loss = (g_sp_sum + 0.6931471805599453f * (float)(g_valid_cnt - g_gold_cnt)) / nv;
        out[0] = loss;
        out[1] = (float)right / (float)TOPK;
    }
}

// ---------------- launch ----------------
extern "C" void kernel_launch(void* const* d_in, const int* in_sizes, int n_in,
                              void* d_out, int out_size) {
    const float* hidden  = (const float*)d_in[0];
    const float* tw      = (const float*)d_in[1];
    const float* w_in    = (const float*)d_in[2];
    const float* b_in    = (const float*)d_in[3];
    const float* score_w = (const float*)d_in[4];
    const float* score_b = (const float*)d_in[5];
    const int*   seq_len = (const int*)d_in[6];
    const int*   gold    = (const int*)d_in[7];
    float* out = (float*)d_out;

    k_query <<<Hh, 256>>>(w_in, tw, b_in);
    k_ef    <<<NTOK / 8, 256>>>(hidden, score_w);
    k_scores<<<NTOK / 256, 256>>>(score_b, seq_len, gold);
    k_reduce<<<64, 1024>>>();
    k_scan2 <<<1, 1024>>>();
    k_count <<<148, 256>>>(seq_len, gold);
    k_final <<<1, 1024>>>(seq_len, gold, out);
}